// round 15
// baseline (speedup 1.0000x reference)
#include <cuda_runtime.h>
#include <cuda_fp16.h>
#include <math.h>
#include <cstdint>

// ---------------------------------------------------------------------------
// Problem constants
// ---------------------------------------------------------------------------
#define Bq      2
#define Sq      2048
#define Dq      2048
#define NH      16
#define NKV     4
#define HD      128
#define QKV_O   3072
#define MROWS   (Bq * Sq)
#define NEG_INF_F (-1e9f)

// softmax scale folded with log2(e): applied to Q at projection time
#define KSCALE2 0.12751741f

// Projection GEMM tiling: CTA 256x128, warp tile 64x64 (4Mx2N warps)
#define BM 256
#define BN 128
#define BK 64
#define NTHREADS 256
#define PST 72
#define A_STG (BM * PST)
#define B_STG (BN * PST)
#define NSTAGE 4
#define MM_SMEM (NSTAGE * (A_STG + B_STG) * 2)   // 221184 B

// Flash kernel: Q + double-buffered K/V (5 tiles), stride FW halfs
#define FW 136
#define TILE_H (128 * FW)
#define FLASH_SMEM (5 * TILE_H * 2)              // 174080 B

// ---------------------------------------------------------------------------
// Static scratch
// ---------------------------------------------------------------------------
__device__ __half g_xh [(size_t)MROWS * Dq];
__device__ __half g_wqh[(size_t)QKV_O * Dq];
__device__ __half g_woh[(size_t)Dq * Dq];
__device__ __half g_q  [(size_t)Bq * NH  * Sq * HD];   // pre-scaled by KSCALE2
__device__ __half g_k  [(size_t)Bq * NKV * Sq * HD];
__device__ __half g_v  [(size_t)Bq * NKV * Sq * HD];
__device__ __half g_o  [(size_t)MROWS * Dq];
__device__ float2 g_tb [(size_t)Sq * (HD / 2)];

// ---------------------------------------------------------------------------
// Helpers
// ---------------------------------------------------------------------------
__device__ __forceinline__ void mma_f16(float (&d)[4], const uint32_t (&a)[4],
                                        const uint32_t* b) {
    asm volatile(
        "mma.sync.aligned.m16n8k16.row.col.f32.f16.f16.f32 "
        "{%0,%1,%2,%3}, {%4,%5,%6,%7}, {%8,%9}, {%0,%1,%2,%3};"
        : "+f"(d[0]), "+f"(d[1]), "+f"(d[2]), "+f"(d[3])
        : "r"(a[0]), "r"(a[1]), "r"(a[2]), "r"(a[3]), "r"(b[0]), "r"(b[1]));
}

__device__ __forceinline__ void ldsm_x4(uint32_t* r, uint32_t addr) {
    asm volatile("ldmatrix.sync.aligned.m8n8.x4.shared.b16 {%0,%1,%2,%3}, [%4];"
        : "=r"(r[0]), "=r"(r[1]), "=r"(r[2]), "=r"(r[3]) : "r"(addr));
}
__device__ __forceinline__ void ldsm_x4_t(uint32_t* r, uint32_t addr) {
    asm volatile("ldmatrix.sync.aligned.m8n8.x4.trans.shared.b16 {%0,%1,%2,%3}, [%4];"
        : "=r"(r[0]), "=r"(r[1]), "=r"(r[2]), "=r"(r[3]) : "r"(addr));
}

__device__ __forceinline__ uint32_t pack_f16x2(float lo, float hi) {
    uint32_t u;
    asm("cvt.rn.f16x2.f32 %0, %1, %2;" : "=r"(u) : "f"(hi), "f"(lo));
    return u;
}

__device__ __forceinline__ void cp16(uint32_t dst, const void* src) {
    asm volatile("cp.async.ca.shared.global [%0], [%1], 16;" :: "r"(dst), "l"(src));
}
#define CP_COMMIT() asm volatile("cp.async.commit_group;" ::: "memory")
#define CP_WAIT0()  asm volatile("cp.async.wait_group 0;" ::: "memory")
#define CP_WAIT1()  asm volatile("cp.async.wait_group 1;" ::: "memory")
#define CP_WAIT2()  asm volatile("cp.async.wait_group 2;" ::: "memory")

// ---------------------------------------------------------------------------
// fp32 -> fp16 conversion pass
// ---------------------------------------------------------------------------
__global__ void k_cvt(const float* __restrict__ src, __half* __restrict__ dst)
{
    size_t i = ((size_t)blockIdx.x * 256 + threadIdx.x) * 4;
    float4 v = *reinterpret_cast<const float4*>(src + i);
    __half2* d = reinterpret_cast<__half2*>(dst + i);
    d[0] = __floats2half2_rn(v.x, v.y);
    d[1] = __floats2half2_rn(v.z, v.w);
}

// ---------------------------------------------------------------------------
// RoPE trig table
// ---------------------------------------------------------------------------
__global__ void k_trig()
{
    const int s = blockIdx.x, i = threadIdx.x;
    double invf = pow(10000.0, -((double)(2 * i) / (double)HD));
    double ang  = (double)s * invf;
    g_tb[(size_t)s * (HD / 2) + i] = make_float2((float)cos(ang), (float)sin(ang));
}

// ---------------------------------------------------------------------------
// Projection NT GEMM tile: C(256x128), warp 64x64, 4-stage cp.async
// ---------------------------------------------------------------------------
__device__ __forceinline__ void mm_tile(const __half* __restrict__ A, int lda,
                                        const __half* __restrict__ B, int ldb,
                                        int kCount, float (&acc)[4][8][4],
                                        __half* sm)
{
    __half* As = sm;
    __half* Bs = sm + NSTAGE * A_STG;

    const int tid  = threadIdx.x;
    const int lane = tid & 31;
    const int wid  = tid >> 5;
    const int wm   = wid >> 1;
    const int wn   = wid & 1;

    const uint32_t asb = (uint32_t)__cvta_generic_to_shared(As);
    const uint32_t bsb = (uint32_t)__cvta_generic_to_shared(Bs);

    uint32_t aA[4];
    const int arow = wm * 64 + (lane & 7) + ((lane >> 3) & 1) * 8;
    const int akoff = ((lane >> 4) & 1) * 8;
#pragma unroll
    for (int mi = 0; mi < 4; mi++)
        aA[mi] = asb + (((arow + mi * 16) * PST + akoff) << 1);
    uint32_t bA[4];
#pragma unroll
    for (int pi = 0; pi < 4; pi++) {
        const int nrow = wn * 64 + pi * 16 + (lane & 7) + ((lane >> 4) & 1) * 8;
        bA[pi] = bsb + ((nrow * PST + ((lane >> 3) & 1) * 8) << 1);
    }

    auto stage = [&](int st, int k0) {
        const uint32_t ao = asb + (uint32_t)st * (A_STG * 2);
        const uint32_t bo = bsb + (uint32_t)st * (B_STG * 2);
#pragma unroll
        for (int t = 0; t < 8; t++) {
            const int u = tid + t * 256;
            const int row = u >> 3, seg = (u & 7) << 3;
            cp16(ao + ((uint32_t)(row * PST + seg) << 1),
                 A + (size_t)row * lda + k0 + seg);
        }
#pragma unroll
        for (int t = 0; t < 4; t++) {
            const int u = tid + t * 256;
            const int row = u >> 3, seg = (u & 7) << 3;
            cp16(bo + ((uint32_t)(row * PST + seg) << 1),
                 B + (size_t)row * ldb + k0 + seg);
        }
        CP_COMMIT();
    };

    const int nch = kCount / BK;
    stage(0, 0);
    if (nch > 1) stage(1, BK);
    if (nch > 2) stage(2, 2 * BK);

    for (int i = 0; i < nch; i++) {
        const int rem = nch - 1 - i;       // groups pending beyond i
        if (rem >= 2) CP_WAIT2(); else if (rem == 1) CP_WAIT1(); else CP_WAIT0();
        __syncthreads();
        if (i + 3 < nch) stage((i + 3) & 3, (i + 3) * BK);

        const uint32_t soA = (uint32_t)(i & 3) * (A_STG * 2);
        const uint32_t soB = (uint32_t)(i & 3) * (B_STG * 2);
#pragma unroll
        for (int ks = 0; ks < BK; ks += 16) {
            uint32_t af[4][4];
#pragma unroll
            for (int mi = 0; mi < 4; mi++)
                ldsm_x4(af[mi], aA[mi] + soA + ks * 2);
#pragma unroll
            for (int pi = 0; pi < 4; pi++) {
                uint32_t bq[4];
                ldsm_x4(bq, bA[pi] + soB + ks * 2);
#pragma unroll
                for (int mi = 0; mi < 4; mi++) {
                    mma_f16(acc[mi][2 * pi],     af[mi], bq);
                    mma_f16(acc[mi][2 * pi + 1], af[mi], bq + 2);
                }
            }
        }
    }
}

// ---------------------------------------------------------------------------
// 1) QKV projection with fused RoPE epilogue; Q heads pre-scaled by KSCALE2.
// ---------------------------------------------------------------------------
__global__ void __launch_bounds__(NTHREADS) k_gemm_qkv()
{
    extern __shared__ __half smg[];
    const int m0 = blockIdx.y * BM, n0 = blockIdx.x * BN;
    float acc[4][8][4] = {};
    mm_tile(g_xh + (size_t)m0 * Dq, Dq, g_wqh + (size_t)n0 * Dq, Dq, Dq, acc, smg);

    const int lane = threadIdx.x & 31, wid = threadIdx.x >> 5;
    const int wm = wid >> 1, wn = wid & 1, r = lane >> 2, c = lane & 3;
    const int nt = blockIdx.x;

    __half* dstbase;
    bool rope;
    if (nt < 16)      { dstbase = g_q; rope = true;  }
    else if (nt < 20) { dstbase = g_k; rope = true;  }
    else              { dstbase = g_v; rope = false; }
    const int hloc = (nt < 16) ? nt : (nt < 20 ? nt - 16 : nt - 20);
    const int nheads = (nt < 16) ? NH : NKV;
    const float qs = (nt < 16) ? KSCALE2 : 1.0f;   // fold softmax scale into Q

#pragma unroll
    for (int mi = 0; mi < 4; mi++) {
        const int m = m0 + wm * 64 + mi * 16 + r;
        const int b = m >> 11, s = m & (Sq - 1);
#pragma unroll
        for (int ni = 0; ni < 8; ni++) {
            const int d = wn * 64 + ni * 8 + 2 * c;
            const int i = d >> 1;
            __half2* p0 = reinterpret_cast<__half2*>(
                dstbase + ((size_t)(b * nheads + hloc) * Sq + s) * HD + d);
            __half2* p1 = reinterpret_cast<__half2*>(
                dstbase + ((size_t)(b * nheads + hloc) * Sq + s + 8) * HD + d);
            float a0 = acc[mi][ni][0], a1 = acc[mi][ni][1];
            float a2 = acc[mi][ni][2], a3 = acc[mi][ni][3];
            if (rope) {
                float2 t0 = g_tb[(size_t)s * (HD / 2) + i];
                float2 t1 = g_tb[(size_t)(s + 8) * (HD / 2) + i];
                float r0 = a0 * t0.x - a1 * t0.y, r1 = a0 * t0.y + a1 * t0.x;
                float r2 = a2 * t1.x - a3 * t1.y, r3 = a2 * t1.y + a3 * t1.x;
                a0 = r0 * qs; a1 = r1 * qs; a2 = r2 * qs; a3 = r3 * qs;
            }
            *p0 = __floats2half2_rn(a0, a1);
            *p1 = __floats2half2_rn(a2, a3);
        }
    }
}

// ---------------------------------------------------------------------------
// 2) Flash attention: R14 structure; scores arrive pre-scaled (base-2 ready).
// ---------------------------------------------------------------------------
__global__ void __launch_bounds__(NTHREADS, 1) k_flash()
{
    extern __shared__ __half smf[];
    const uint32_t sb  = (uint32_t)__cvta_generic_to_shared(smf);
    const uint32_t qsb = sb;
    const uint32_t k0b = sb + 1 * TILE_H * 2;
    const uint32_t v0b = sb + 3 * TILE_H * 2;
    const uint32_t BUFB = TILE_H * 2;

    const int it = 15 - blockIdx.x;               // heavy tiles first
    const int bh = blockIdx.y;
    const int b = bh >> 4, h = bh & 15, hk = h >> 2;
    const int tid = threadIdx.x, lane = tid & 31, w = tid >> 5;
    const int r = lane >> 2, c = lane & 3;
    const int m0 = w * 16 + r;

    const int frow = w * 16 + (lane & 7) + ((lane >> 3) & 1) * 8;
    const uint32_t aQ = qsb + ((frow * FW + ((lane >> 4) & 1) * 8) << 1);
    uint32_t bK[8];
#pragma unroll
    for (int pi = 0; pi < 8; pi++) {
        const int nrow = pi * 16 + (lane & 7) + ((lane >> 4) & 1) * 8;
        bK[pi] = k0b + ((nrow * FW + ((lane >> 3) & 1) * 8) << 1);
    }
    const int jrow = (lane & 7) + ((lane >> 3) & 1) * 8;
    uint32_t bV[8];
#pragma unroll
    for (int pi = 0; pi < 8; pi++)
        bV[pi] = v0b + ((jrow * FW + pi * 16 + ((lane >> 4) & 1) * 8) << 1);

    const __half* KB = g_k + (size_t)(b * NKV + hk) * Sq * HD;
    const __half* VB = g_v + (size_t)(b * NKV + hk) * Sq * HD;

    // Prologue: Q + K(0) + V(0), single commit group
    const __half* Qp = g_q + ((size_t)bh * Sq + (size_t)it * 128) * HD;
#pragma unroll
    for (int i = 0; i < 8; i++) {
        int f = tid + i * 256;
        int m = f >> 4, d8 = (f & 15) << 3;
        cp16(qsb + ((uint32_t)(m * FW + d8) << 1), Qp + (size_t)m * HD + d8);
        cp16(k0b + ((uint32_t)(m * FW + d8) << 1), KB + (size_t)m * HD + d8);
        cp16(v0b + ((uint32_t)(m * FW + d8) << 1), VB + (size_t)m * HD + d8);
    }
    CP_COMMIT();

    float acc_o[16][4] = {};
    float mprev0 = -1e30f, mprev1 = -1e30f;
    float l0 = 0.f, l1 = 0.f;

    for (int jt = 0; jt <= it; jt++) {
        CP_WAIT0();
        __syncthreads();
        const uint32_t kb = (uint32_t)(jt & 1) * BUFB;
        const uint32_t vb = (uint32_t)(jt & 1) * BUFB;

        if (jt < it) {
            const uint32_t nb = (uint32_t)((jt + 1) & 1) * BUFB;
#pragma unroll
            for (int i = 0; i < 8; i++) {
                int f = tid + i * 256;
                int n = f >> 4, d8 = (f & 15) << 3;
                cp16(k0b + nb + ((uint32_t)(n * FW + d8) << 1),
                     KB + (size_t)((jt + 1) * 128 + n) * HD + d8);
                cp16(v0b + nb + ((uint32_t)(n * FW + d8) << 1),
                     VB + (size_t)((jt + 1) * 128 + n) * HD + d8);
            }
            CP_COMMIT();
        }

        // S = Q K^T (already scaled by KSCALE2 via Q)
        float acc_s[16][4] = {};
#pragma unroll
        for (int kc = 0; kc < 128; kc += 16) {
            uint32_t a[4];
            ldsm_x4(a, aQ + kc * 2);
#pragma unroll
            for (int pi = 0; pi < 8; pi++) {
                uint32_t bq[4];
                ldsm_x4(bq, bK[pi] + kb + kc * 2);
                mma_f16(acc_s[2 * pi],     a, bq);
                mma_f16(acc_s[2 * pi + 1], a, bq + 2);
            }
        }

        // Online softmax in base-2 (no per-element scale multiply)
        float tmax0 = -3.4e38f, tmax1 = -3.4e38f;
#pragma unroll
        for (int ni = 0; ni < 16; ni++) {
#pragma unroll
            for (int q = 0; q < 4; q++) {
                float v = acc_s[ni][q];
                if (jt == it) {
                    int n = ni * 8 + 2 * c + (q & 1);
                    int m = m0 + 8 * (q >> 1);
                    if (n > m) v = NEG_INF_F;
                }
                acc_s[ni][q] = v;
                if (q < 2) tmax0 = fmaxf(tmax0, v); else tmax1 = fmaxf(tmax1, v);
            }
        }
#pragma unroll
        for (int o = 1; o <= 2; o <<= 1) {
            tmax0 = fmaxf(tmax0, __shfl_xor_sync(0xFFFFFFFFu, tmax0, o));
            tmax1 = fmaxf(tmax1, __shfl_xor_sync(0xFFFFFFFFu, tmax1, o));
        }
        const float mn0 = fmaxf(mprev0, tmax0);
        const float mn1 = fmaxf(mprev1, tmax1);
        const float fc0 = exp2f(mprev0 - mn0);
        const float fc1 = exp2f(mprev1 - mn1);
        mprev0 = mn0; mprev1 = mn1;

        uint32_t plo[16], phi[16];
        float s0 = 0.f, s1 = 0.f;
#pragma unroll
        for (int ni = 0; ni < 16; ni++) {
            float p0 = exp2f(acc_s[ni][0] - mn0);
            float p1 = exp2f(acc_s[ni][1] - mn0);
            float p2 = exp2f(acc_s[ni][2] - mn1);
            float p3 = exp2f(acc_s[ni][3] - mn1);
            s0 += p0 + p1; s1 += p2 + p3;
            plo[ni] = pack_f16x2(p0, p1);
            phi[ni] = pack_f16x2(p2, p3);
        }
#pragma unroll
        for (int o = 1; o <= 2; o <<= 1) {
            s0 += __shfl_xor_sync(0xFFFFFFFFu, s0, o);
            s1 += __shfl_xor_sync(0xFFFFFFFFu, s1, o);
        }
        l0 = l0 * fc0 + s0;
        l1 = l1 * fc1 + s1;
#pragma unroll
        for (int ni = 0; ni < 16; ni++) {
            acc_o[ni][0] *= fc0; acc_o[ni][1] *= fc0;
            acc_o[ni][2] *= fc1; acc_o[ni][3] *= fc1;
        }

        // O += P~ V — V(jt) already resident
#pragma unroll
        for (int kc = 0; kc < 128; kc += 16) {
            const int ni0 = kc >> 3;
            uint32_t a[4] = { plo[ni0], phi[ni0], plo[ni0 + 1], phi[ni0 + 1] };
            const uint32_t vo = vb + ((uint32_t)(kc * FW) << 1);
#pragma unroll
            for (int pi = 0; pi < 8; pi++) {
                uint32_t bq[4];
                ldsm_x4_t(bq, bV[pi] + vo);
                mma_f16(acc_o[2 * pi],     a, bq);
                mma_f16(acc_o[2 * pi + 1], a, bq + 2);
            }
        }
    }

    // Epilogue
    const float i0 = 1.f / l0, i1 = 1.f / l1;
    const int srow = it * 128 + m0;
    __half* o0 = g_o + ((size_t)b * Sq + srow) * Dq + h * HD;
    __half* o1 = g_o + ((size_t)b * Sq + srow + 8) * Dq + h * HD;
#pragma unroll
    for (int ni = 0; ni < 16; ni++) {
        const int d = ni * 8 + 2 * c;
        *reinterpret_cast<__half2*>(o0 + d) =
            __floats2half2_rn(acc_o[ni][0] * i0, acc_o[ni][1] * i0);
        *reinterpret_cast<__half2*>(o1 + d) =
            __floats2half2_rn(acc_o[ni][2] * i1, acc_o[ni][3] * i1);
    }
}

// ---------------------------------------------------------------------------
// 3) Output projection (half in, fp32 out)
// ---------------------------------------------------------------------------
__global__ void __launch_bounds__(NTHREADS) k_gemm_out(float* __restrict__ out)
{
    extern __shared__ __half smg[];
    const int m0 = blockIdx.y * BM, n0 = blockIdx.x * BN;
    float acc[4][8][4] = {};
    mm_tile(g_o + (size_t)m0 * Dq, Dq, g_woh + (size_t)n0 * Dq, Dq, Dq, acc, smg);

    const int lane = threadIdx.x & 31, wid = threadIdx.x >> 5;
    const int wm = wid >> 1, wn = wid & 1, r = lane >> 2, c = lane & 3;
#pragma unroll
    for (int mi = 0; mi < 4; mi++) {
        const int m = m0 + wm * 64 + mi * 16 + r;
#pragma unroll
        for (int ni = 0; ni < 8; ni++) {
            const int n = n0 + wn * 64 + ni * 8 + 2 * c;
            *reinterpret_cast<float2*>(out + (size_t)m * Dq + n) =
                make_float2(acc[mi][ni][0], acc[mi][ni][1]);
            *reinterpret_cast<float2*>(out + (size_t)(m + 8) * Dq + n) =
                make_float2(acc[mi][ni][2], acc[mi][ni][3]);
        }
    }
}

// ---------------------------------------------------------------------------
// Launch
// ---------------------------------------------------------------------------
extern "C" void kernel_launch(void* const* d_in, const int* in_sizes, int n_in,
                              void* d_out, int out_size)
{
    const float* x     = (const float*)d_in[0];
    const float* w_qkv = (const float*)d_in[1];
    const float* w_o   = (const float*)d_in[2];
    float* out = (float*)d_out;

    __half *xh, *wqh, *woh;
    cudaGetSymbolAddress((void**)&xh,  g_xh);
    cudaGetSymbolAddress((void**)&wqh, g_wqh);
    cudaGetSymbolAddress((void**)&woh, g_woh);
    cudaFuncSetAttribute(k_flash,    cudaFuncAttributeMaxDynamicSharedMemorySize, FLASH_SMEM);
    cudaFuncSetAttribute(k_gemm_qkv, cudaFuncAttributeMaxDynamicSharedMemorySize, MM_SMEM);
    cudaFuncSetAttribute(k_gemm_out, cudaFuncAttributeMaxDynamicSharedMemorySize, MM_SMEM);

    k_cvt<<<(unsigned)((size_t)MROWS * Dq / 1024), 256>>>(x, xh);
    k_cvt<<<(unsigned)((size_t)QKV_O * Dq / 1024), 256>>>(w_qkv, wqh);
    k_cvt<<<(unsigned)((size_t)Dq * Dq / 1024), 256>>>(w_o, woh);
    k_trig<<<Sq, HD / 2>>>();

    k_gemm_qkv<<<dim3(QKV_O / BN, MROWS / BM), NTHREADS, MM_SMEM>>>();
    k_flash<<<dim3(16, Bq * NH), NTHREADS, FLASH_SMEM>>>();
    k_gemm_out<<<dim3(Dq / BN, MROWS / BM), NTHREADS, MM_SMEM>>>(out);
}

// round 16
// speedup vs baseline: 1.1196x; 1.1196x over previous
#include <cuda_runtime.h>
#include <cuda_fp16.h>
#include <math.h>
#include <cstdint>

// ---------------------------------------------------------------------------
// Problem constants
// ---------------------------------------------------------------------------
#define Bq      2
#define Sq      2048
#define Dq      2048
#define NH      16
#define NKV     4
#define HD      128
#define QKV_O   3072
#define MROWS   (Bq * Sq)
#define NEG_INF_F (-1e9f)

// softmax scale folded with log2(e): applied to Q at projection time
#define KSCALE2 0.12751741f

// Projection GEMM tiling: CTA 256x128, warp tile 64x64 (4Mx2N warps)
#define BM 256
#define BN 128
#define BK 64
#define NTHREADS 256
#define PST 72
#define A_STG (BM * PST)
#define B_STG (BN * PST)
#define NSTAGE 3
#define MM_SMEM (NSTAGE * (A_STG + B_STG) * 2)   // 165888 B

// Flash kernel: Q + double-buffered K/V (5 tiles), stride FW halfs
#define FW 136
#define TILE_H (128 * FW)
#define FLASH_SMEM (5 * TILE_H * 2)              // 174080 B

// ---------------------------------------------------------------------------
// Static scratch
// ---------------------------------------------------------------------------
__device__ __half g_xh [(size_t)MROWS * Dq];
__device__ __half g_wqh[(size_t)QKV_O * Dq];
__device__ __half g_woh[(size_t)Dq * Dq];
__device__ __half g_q  [(size_t)Bq * NH  * Sq * HD];   // pre-scaled by KSCALE2
__device__ __half g_k  [(size_t)Bq * NKV * Sq * HD];
__device__ __half g_v  [(size_t)Bq * NKV * Sq * HD];
__device__ __half g_o  [(size_t)MROWS * Dq];
__device__ float2 g_tb [(size_t)Sq * (HD / 2)];

// ---------------------------------------------------------------------------
// Helpers
// ---------------------------------------------------------------------------
__device__ __forceinline__ void mma_f16(float (&d)[4], const uint32_t (&a)[4],
                                        const uint32_t* b) {
    asm volatile(
        "mma.sync.aligned.m16n8k16.row.col.f32.f16.f16.f32 "
        "{%0,%1,%2,%3}, {%4,%5,%6,%7}, {%8,%9}, {%0,%1,%2,%3};"
        : "+f"(d[0]), "+f"(d[1]), "+f"(d[2]), "+f"(d[3])
        : "r"(a[0]), "r"(a[1]), "r"(a[2]), "r"(a[3]), "r"(b[0]), "r"(b[1]));
}

__device__ __forceinline__ void ldsm_x4(uint32_t* r, uint32_t addr) {
    asm volatile("ldmatrix.sync.aligned.m8n8.x4.shared.b16 {%0,%1,%2,%3}, [%4];"
        : "=r"(r[0]), "=r"(r[1]), "=r"(r[2]), "=r"(r[3]) : "r"(addr));
}
__device__ __forceinline__ void ldsm_x4_t(uint32_t* r, uint32_t addr) {
    asm volatile("ldmatrix.sync.aligned.m8n8.x4.trans.shared.b16 {%0,%1,%2,%3}, [%4];"
        : "=r"(r[0]), "=r"(r[1]), "=r"(r[2]), "=r"(r[3]) : "r"(addr));
}

__device__ __forceinline__ uint32_t pack_f16x2(float lo, float hi) {
    uint32_t u;
    asm("cvt.rn.f16x2.f32 %0, %1, %2;" : "=r"(u) : "f"(hi), "f"(lo));
    return u;
}

__device__ __forceinline__ void cp16(uint32_t dst, const void* src) {
    asm volatile("cp.async.ca.shared.global [%0], [%1], 16;" :: "r"(dst), "l"(src));
}
#define CP_COMMIT() asm volatile("cp.async.commit_group;" ::: "memory")
#define CP_WAIT0()  asm volatile("cp.async.wait_group 0;" ::: "memory")
#define CP_WAIT1()  asm volatile("cp.async.wait_group 1;" ::: "memory")

// ---------------------------------------------------------------------------
// fp32 -> fp16 conversion pass
// ---------------------------------------------------------------------------
__global__ void k_cvt(const float* __restrict__ src, __half* __restrict__ dst)
{
    size_t i = ((size_t)blockIdx.x * 256 + threadIdx.x) * 4;
    float4 v = *reinterpret_cast<const float4*>(src + i);
    __half2* d = reinterpret_cast<__half2*>(dst + i);
    d[0] = __floats2half2_rn(v.x, v.y);
    d[1] = __floats2half2_rn(v.z, v.w);
}

// ---------------------------------------------------------------------------
// RoPE trig table
// ---------------------------------------------------------------------------
__global__ void k_trig()
{
    const int s = blockIdx.x, i = threadIdx.x;
    double invf = pow(10000.0, -((double)(2 * i) / (double)HD));
    double ang  = (double)s * invf;
    g_tb[(size_t)s * (HD / 2) + i] = make_float2((float)cos(ang), (float)sin(ang));
}

// ---------------------------------------------------------------------------
// Projection NT GEMM tile: C(256x128), warp 64x64, 3-stage cp.async
// ---------------------------------------------------------------------------
__device__ __forceinline__ void mm_tile(const __half* __restrict__ A, int lda,
                                        const __half* __restrict__ B, int ldb,
                                        int kCount, float (&acc)[4][8][4],
                                        __half* sm)
{
    __half* As = sm;
    __half* Bs = sm + NSTAGE * A_STG;

    const int tid  = threadIdx.x;
    const int lane = tid & 31;
    const int wid  = tid >> 5;
    const int wm   = wid >> 1;
    const int wn   = wid & 1;

    const uint32_t asb = (uint32_t)__cvta_generic_to_shared(As);
    const uint32_t bsb = (uint32_t)__cvta_generic_to_shared(Bs);

    uint32_t aA[4];
    const int arow = wm * 64 + (lane & 7) + ((lane >> 3) & 1) * 8;
    const int akoff = ((lane >> 4) & 1) * 8;
#pragma unroll
    for (int mi = 0; mi < 4; mi++)
        aA[mi] = asb + (((arow + mi * 16) * PST + akoff) << 1);
    uint32_t bA[4];
#pragma unroll
    for (int pi = 0; pi < 4; pi++) {
        const int nrow = wn * 64 + pi * 16 + (lane & 7) + ((lane >> 4) & 1) * 8;
        bA[pi] = bsb + ((nrow * PST + ((lane >> 3) & 1) * 8) << 1);
    }

    auto stage = [&](int st, int k0) {
        const uint32_t ao = asb + (uint32_t)st * (A_STG * 2);
        const uint32_t bo = bsb + (uint32_t)st * (B_STG * 2);
#pragma unroll
        for (int t = 0; t < 8; t++) {
            const int u = tid + t * 256;
            const int row = u >> 3, seg = (u & 7) << 3;
            cp16(ao + ((uint32_t)(row * PST + seg) << 1),
                 A + (size_t)row * lda + k0 + seg);
        }
#pragma unroll
        for (int t = 0; t < 4; t++) {
            const int u = tid + t * 256;
            const int row = u >> 3, seg = (u & 7) << 3;
            cp16(bo + ((uint32_t)(row * PST + seg) << 1),
                 B + (size_t)row * ldb + k0 + seg);
        }
        CP_COMMIT();
    };

    const int nch = kCount / BK;
    stage(0, 0);
    if (nch > 1) stage(1, BK);

    for (int i = 0; i < nch; i++) {
        if (i + 1 < nch) CP_WAIT1(); else CP_WAIT0();
        __syncthreads();
        if (i + 2 < nch) stage((i + 2) % NSTAGE, (i + 2) * BK);

        const uint32_t soA = (uint32_t)(i % NSTAGE) * (A_STG * 2);
        const uint32_t soB = (uint32_t)(i % NSTAGE) * (B_STG * 2);
#pragma unroll
        for (int ks = 0; ks < BK; ks += 16) {
            uint32_t af[4][4];
#pragma unroll
            for (int mi = 0; mi < 4; mi++)
                ldsm_x4(af[mi], aA[mi] + soA + ks * 2);
#pragma unroll
            for (int pi = 0; pi < 4; pi++) {
                uint32_t bq[4];
                ldsm_x4(bq, bA[pi] + soB + ks * 2);
#pragma unroll
                for (int mi = 0; mi < 4; mi++) {
                    mma_f16(acc[mi][2 * pi],     af[mi], bq);
                    mma_f16(acc[mi][2 * pi + 1], af[mi], bq + 2);
                }
            }
        }
    }
}

// ---------------------------------------------------------------------------
// 1) QKV projection with fused RoPE epilogue; Q heads pre-scaled by KSCALE2.
// ---------------------------------------------------------------------------
__global__ void __launch_bounds__(NTHREADS) k_gemm_qkv()
{
    extern __shared__ __half smg[];
    const int m0 = blockIdx.y * BM, n0 = blockIdx.x * BN;
    float acc[4][8][4] = {};
    mm_tile(g_xh + (size_t)m0 * Dq, Dq, g_wqh + (size_t)n0 * Dq, Dq, Dq, acc, smg);

    const int lane = threadIdx.x & 31, wid = threadIdx.x >> 5;
    const int wm = wid >> 1, wn = wid & 1, r = lane >> 2, c = lane & 3;
    const int nt = blockIdx.x;

    __half* dstbase;
    bool rope;
    if (nt < 16)      { dstbase = g_q; rope = true;  }
    else if (nt < 20) { dstbase = g_k; rope = true;  }
    else              { dstbase = g_v; rope = false; }
    const int hloc = (nt < 16) ? nt : (nt < 20 ? nt - 16 : nt - 20);
    const int nheads = (nt < 16) ? NH : NKV;
    const float qs = (nt < 16) ? KSCALE2 : 1.0f;   // fold softmax scale into Q

#pragma unroll
    for (int mi = 0; mi < 4; mi++) {
        const int m = m0 + wm * 64 + mi * 16 + r;
        const int b = m >> 11, s = m & (Sq - 1);
#pragma unroll
        for (int ni = 0; ni < 8; ni++) {
            const int d = wn * 64 + ni * 8 + 2 * c;
            const int i = d >> 1;
            __half2* p0 = reinterpret_cast<__half2*>(
                dstbase + ((size_t)(b * nheads + hloc) * Sq + s) * HD + d);
            __half2* p1 = reinterpret_cast<__half2*>(
                dstbase + ((size_t)(b * nheads + hloc) * Sq + s + 8) * HD + d);
            float a0 = acc[mi][ni][0], a1 = acc[mi][ni][1];
            float a2 = acc[mi][ni][2], a3 = acc[mi][ni][3];
            if (rope) {
                float2 t0 = g_tb[(size_t)s * (HD / 2) + i];
                float2 t1 = g_tb[(size_t)(s + 8) * (HD / 2) + i];
                float r0 = a0 * t0.x - a1 * t0.y, r1 = a0 * t0.y + a1 * t0.x;
                float r2 = a2 * t1.x - a3 * t1.y, r3 = a2 * t1.y + a3 * t1.x;
                a0 = r0 * qs; a1 = r1 * qs; a2 = r2 * qs; a3 = r3 * qs;
            }
            *p0 = __floats2half2_rn(a0, a1);
            *p1 = __floats2half2_rn(a2, a3);
        }
    }
}

// ---------------------------------------------------------------------------
// 2) Flash attention: R14 structure; scores arrive pre-scaled (base-2 ready).
// ---------------------------------------------------------------------------
__global__ void __launch_bounds__(NTHREADS, 1) k_flash()
{
    extern __shared__ __half smf[];
    const uint32_t sb  = (uint32_t)__cvta_generic_to_shared(smf);
    const uint32_t qsb = sb;
    const uint32_t k0b = sb + 1 * TILE_H * 2;
    const uint32_t v0b = sb + 3 * TILE_H * 2;
    const uint32_t BUFB = TILE_H * 2;

    const int it = 15 - blockIdx.x;               // heavy tiles first
    const int bh = blockIdx.y;
    const int b = bh >> 4, h = bh & 15, hk = h >> 2;
    const int tid = threadIdx.x, lane = tid & 31, w = tid >> 5;
    const int r = lane >> 2, c = lane & 3;
    const int m0 = w * 16 + r;

    const int frow = w * 16 + (lane & 7) + ((lane >> 3) & 1) * 8;
    const uint32_t aQ = qsb + ((frow * FW + ((lane >> 4) & 1) * 8) << 1);
    uint32_t bK[8];
#pragma unroll
    for (int pi = 0; pi < 8; pi++) {
        const int nrow = pi * 16 + (lane & 7) + ((lane >> 4) & 1) * 8;
        bK[pi] = k0b + ((nrow * FW + ((lane >> 3) & 1) * 8) << 1);
    }
    const int jrow = (lane & 7) + ((lane >> 3) & 1) * 8;
    uint32_t bV[8];
#pragma unroll
    for (int pi = 0; pi < 8; pi++)
        bV[pi] = v0b + ((jrow * FW + pi * 16 + ((lane >> 4) & 1) * 8) << 1);

    const __half* KB = g_k + (size_t)(b * NKV + hk) * Sq * HD;
    const __half* VB = g_v + (size_t)(b * NKV + hk) * Sq * HD;

    // Prologue: Q + K(0) + V(0), single commit group
    const __half* Qp = g_q + ((size_t)bh * Sq + (size_t)it * 128) * HD;
#pragma unroll
    for (int i = 0; i < 8; i++) {
        int f = tid + i * 256;
        int m = f >> 4, d8 = (f & 15) << 3;
        cp16(qsb + ((uint32_t)(m * FW + d8) << 1), Qp + (size_t)m * HD + d8);
        cp16(k0b + ((uint32_t)(m * FW + d8) << 1), KB + (size_t)m * HD + d8);
        cp16(v0b + ((uint32_t)(m * FW + d8) << 1), VB + (size_t)m * HD + d8);
    }
    CP_COMMIT();

    float acc_o[16][4] = {};
    float mprev0 = -1e30f, mprev1 = -1e30f;
    float l0 = 0.f, l1 = 0.f;

    for (int jt = 0; jt <= it; jt++) {
        CP_WAIT0();
        __syncthreads();
        const uint32_t kb = (uint32_t)(jt & 1) * BUFB;
        const uint32_t vb = (uint32_t)(jt & 1) * BUFB;

        if (jt < it) {
            const uint32_t nb = (uint32_t)((jt + 1) & 1) * BUFB;
#pragma unroll
            for (int i = 0; i < 8; i++) {
                int f = tid + i * 256;
                int n = f >> 4, d8 = (f & 15) << 3;
                cp16(k0b + nb + ((uint32_t)(n * FW + d8) << 1),
                     KB + (size_t)((jt + 1) * 128 + n) * HD + d8);
                cp16(v0b + nb + ((uint32_t)(n * FW + d8) << 1),
                     VB + (size_t)((jt + 1) * 128 + n) * HD + d8);
            }
            CP_COMMIT();
        }

        // S = Q K^T (already scaled by KSCALE2 via Q)
        float acc_s[16][4] = {};
#pragma unroll
        for (int kc = 0; kc < 128; kc += 16) {
            uint32_t a[4];
            ldsm_x4(a, aQ + kc * 2);
#pragma unroll
            for (int pi = 0; pi < 8; pi++) {
                uint32_t bq[4];
                ldsm_x4(bq, bK[pi] + kb + kc * 2);
                mma_f16(acc_s[2 * pi],     a, bq);
                mma_f16(acc_s[2 * pi + 1], a, bq + 2);
            }
        }

        // Online softmax in base-2 (no per-element scale multiply)
        float tmax0 = -3.4e38f, tmax1 = -3.4e38f;
#pragma unroll
        for (int ni = 0; ni < 16; ni++) {
#pragma unroll
            for (int q = 0; q < 4; q++) {
                float v = acc_s[ni][q];
                if (jt == it) {
                    int n = ni * 8 + 2 * c + (q & 1);
                    int m = m0 + 8 * (q >> 1);
                    if (n > m) v = NEG_INF_F;
                }
                acc_s[ni][q] = v;
                if (q < 2) tmax0 = fmaxf(tmax0, v); else tmax1 = fmaxf(tmax1, v);
            }
        }
#pragma unroll
        for (int o = 1; o <= 2; o <<= 1) {
            tmax0 = fmaxf(tmax0, __shfl_xor_sync(0xFFFFFFFFu, tmax0, o));
            tmax1 = fmaxf(tmax1, __shfl_xor_sync(0xFFFFFFFFu, tmax1, o));
        }
        const float mn0 = fmaxf(mprev0, tmax0);
        const float mn1 = fmaxf(mprev1, tmax1);
        const float fc0 = exp2f(mprev0 - mn0);
        const float fc1 = exp2f(mprev1 - mn1);
        mprev0 = mn0; mprev1 = mn1;

        uint32_t plo[16], phi[16];
        float s0 = 0.f, s1 = 0.f;
#pragma unroll
        for (int ni = 0; ni < 16; ni++) {
            float p0 = exp2f(acc_s[ni][0] - mn0);
            float p1 = exp2f(acc_s[ni][1] - mn0);
            float p2 = exp2f(acc_s[ni][2] - mn1);
            float p3 = exp2f(acc_s[ni][3] - mn1);
            s0 += p0 + p1; s1 += p2 + p3;
            plo[ni] = pack_f16x2(p0, p1);
            phi[ni] = pack_f16x2(p2, p3);
        }
#pragma unroll
        for (int o = 1; o <= 2; o <<= 1) {
            s0 += __shfl_xor_sync(0xFFFFFFFFu, s0, o);
            s1 += __shfl_xor_sync(0xFFFFFFFFu, s1, o);
        }
        l0 = l0 * fc0 + s0;
        l1 = l1 * fc1 + s1;
#pragma unroll
        for (int ni = 0; ni < 16; ni++) {
            acc_o[ni][0] *= fc0; acc_o[ni][1] *= fc0;
            acc_o[ni][2] *= fc1; acc_o[ni][3] *= fc1;
        }

        // O += P~ V — V(jt) already resident
#pragma unroll
        for (int kc = 0; kc < 128; kc += 16) {
            const int ni0 = kc >> 3;
            uint32_t a[4] = { plo[ni0], phi[ni0], plo[ni0 + 1], phi[ni0 + 1] };
            const uint32_t vo = vb + ((uint32_t)(kc * FW) << 1);
#pragma unroll
            for (int pi = 0; pi < 8; pi++) {
                uint32_t bq[4];
                ldsm_x4_t(bq, bV[pi] + vo);
                mma_f16(acc_o[2 * pi],     a, bq);
                mma_f16(acc_o[2 * pi + 1], a, bq + 2);
            }
        }
    }

    // Epilogue
    const float i0 = 1.f / l0, i1 = 1.f / l1;
    const int srow = it * 128 + m0;
    __half* o0 = g_o + ((size_t)b * Sq + srow) * Dq + h * HD;
    __half* o1 = g_o + ((size_t)b * Sq + srow + 8) * Dq + h * HD;
#pragma unroll
    for (int ni = 0; ni < 16; ni++) {
        const int d = ni * 8 + 2 * c;
        *reinterpret_cast<__half2*>(o0 + d) =
            __floats2half2_rn(acc_o[ni][0] * i0, acc_o[ni][1] * i0);
        *reinterpret_cast<__half2*>(o1 + d) =
            __floats2half2_rn(acc_o[ni][2] * i1, acc_o[ni][3] * i1);
    }
}

// ---------------------------------------------------------------------------
// 3) Output projection (half in, fp32 out)
// ---------------------------------------------------------------------------
__global__ void __launch_bounds__(NTHREADS) k_gemm_out(float* __restrict__ out)
{
    extern __shared__ __half smg[];
    const int m0 = blockIdx.y * BM, n0 = blockIdx.x * BN;
    float acc[4][8][4] = {};
    mm_tile(g_o + (size_t)m0 * Dq, Dq, g_woh + (size_t)n0 * Dq, Dq, Dq, acc, smg);

    const int lane = threadIdx.x & 31, wid = threadIdx.x >> 5;
    const int wm = wid >> 1, wn = wid & 1, r = lane >> 2, c = lane & 3;
#pragma unroll
    for (int mi = 0; mi < 4; mi++) {
        const int m = m0 + wm * 64 + mi * 16 + r;
#pragma unroll
        for (int ni = 0; ni < 8; ni++) {
            const int n = n0 + wn * 64 + ni * 8 + 2 * c;
            *reinterpret_cast<float2*>(out + (size_t)m * Dq + n) =
                make_float2(acc[mi][ni][0], acc[mi][ni][1]);
            *reinterpret_cast<float2*>(out + (size_t)(m + 8) * Dq + n) =
                make_float2(acc[mi][ni][2], acc[mi][ni][3]);
        }
    }
}

// ---------------------------------------------------------------------------
// Launch
// ---------------------------------------------------------------------------
extern "C" void kernel_launch(void* const* d_in, const int* in_sizes, int n_in,
                              void* d_out, int out_size)
{
    const float* x     = (const float*)d_in[0];
    const float* w_qkv = (const float*)d_in[1];
    const float* w_o   = (const float*)d_in[2];
    float* out = (float*)d_out;

    __half *xh, *wqh, *woh;
    cudaGetSymbolAddress((void**)&xh,  g_xh);
    cudaGetSymbolAddress((void**)&wqh, g_wqh);
    cudaGetSymbolAddress((void**)&woh, g_woh);
    cudaFuncSetAttribute(k_flash,    cudaFuncAttributeMaxDynamicSharedMemorySize, FLASH_SMEM);
    cudaFuncSetAttribute(k_gemm_qkv, cudaFuncAttributeMaxDynamicSharedMemorySize, MM_SMEM);
    cudaFuncSetAttribute(k_gemm_out, cudaFuncAttributeMaxDynamicSharedMemorySize, MM_SMEM);

    k_cvt<<<(unsigned)((size_t)MROWS * Dq / 1024), 256>>>(x, xh);
    k_cvt<<<(unsigned)((size_t)QKV_O * Dq / 1024), 256>>>(w_qkv, wqh);
    k_cvt<<<(unsigned)((size_t)Dq * Dq / 1024), 256>>>(w_o, woh);
    k_trig<<<Sq, HD / 2>>>();

    k_gemm_qkv<<<dim3(QKV_O / BN, MROWS / BM), NTHREADS, MM_SMEM>>>();
    k_flash<<<dim3(16, Bq * NH), NTHREADS, FLASH_SMEM>>>();
    k_gemm_out<<<dim3(Dq / BN, MROWS / BM), NTHREADS, MM_SMEM>>>(out);
}